// round 7
// baseline (speedup 1.0000x reference)
#include <cuda_runtime.h>

// Problem constants
#define B_   16
#define K_   64
#define BK   1024
#define IN_  128
#define H0   192
#define H1   64
#define UNF  6
#define HS   (H0 + H1)        // 256
#define L2E  1.4426950408889634f
#define RMAX 7
#define NCTA 147              // ceil(1024 / 7)
#define NTHR 576              // 3 warpgroups of 192
#define NP0  96               // i-pairs for H0

typedef unsigned long long u64;

// -------- device scratch --------
// pairwise tanh-folded params (full fp32, packed for f32x2):
//   g_p0a[p*H0+h] = {(s0,s1),(b0,b1)}   s=0.5*sig, b=-0.5*sig*mu, lanes = i=2p, 2p+1
//   g_p0c[p*H0+h] = {(zN0,zN1),(zW0,zW1)}  zN=0.5*relu(w)*erev, zW=0.5*relu(w)
__device__ ulonglong2 g_p0a[NP0 * H0];
__device__ ulonglong2 g_p0c[NP0 * H0];
__device__ float4 g_d1[H1 * H1];     // layer1 recurrent (L1-resident)
__device__ float4 g_din1[H0 * H1];   // layer1 input params
__device__ float4 g_hc0[H0];         // {gl*vleak, gl, 1/(relu(cm)+eps), gdiff*sqrt(dt)}
__device__ float4 g_hc1[H1];
__device__ float2 g_sums0[H0];       // exact column sums {0.5*wz, 0.5*ww}
__device__ float2 g_sums1[H1];
__device__ float2 g_sumsin1[H1];
__device__ float  g_A0n[B_ * H0];
__device__ float  g_A0d[B_ * H0];
__device__ float  g_wts[B_ * K_];
__device__ float  g_s1[BK * H1];
__device__ int    g_cnt[B_];

__device__ __forceinline__ float tanhfast(float x) {
    float r; asm("tanh.approx.f32 %0, %1;" : "=f"(r) : "f"(x)); return r;
}
__device__ __forceinline__ float ex2f(float x) {
    float r; asm("ex2.approx.f32 %0, %1;" : "=f"(r) : "f"(x)); return r;
}
__device__ __forceinline__ float rcpf(float x) {
    float r; asm("rcp.approx.f32 %0, %1;" : "=f"(r) : "f"(x)); return r;
}
__device__ __forceinline__ float relu_(float x) { return x > 0.f ? x : 0.f; }

// ---- packed f32x2 helpers (Blackwell) ----
__device__ __forceinline__ u64 packf2(float a, float b) {
    u64 r;
    asm("mov.b64 %0, {%1, %2};" : "=l"(r) : "r"(__float_as_uint(a)), "r"(__float_as_uint(b)));
    return r;
}
__device__ __forceinline__ void unpackf2(u64 v, float& a, float& b) {
    unsigned lo, hi;
    asm("mov.b64 {%0, %1}, %2;" : "=r"(lo), "=r"(hi) : "l"(v));
    a = __uint_as_float(lo); b = __uint_as_float(hi);
}
__device__ __forceinline__ u64 ffma2(u64 a, u64 b, u64 c) {
    u64 d;
    asm("fma.rn.f32x2 %0, %1, %2, %3;" : "=l"(d) : "l"(a), "l"(b), "l"(c));
    return d;
}
__device__ __forceinline__ ulonglong2 ldcg2u64(const ulonglong2* p) {
    ulonglong2 v;
    asm volatile("ld.global.cg.v2.u64 {%0,%1}, [%2];" : "=l"(v.x), "=l"(v.y) : "l"(p));
    return v;
}

// ================= precompute =================
// ranges: p0a(18432), p0c(18432), d1(4096), din1(12288), hc0(192), hc1(64),
//         sums0(192), sums1(64), sumsin1(64), A0(3072), wts(16), pass(1024), cnt(16)
__global__ void precompute_kernel(
    const float* __restrict__ x, const float* __restrict__ log_weights,
    const float* __restrict__ gleak0, const float* __restrict__ vleak0, const float* __restrict__ cm0,
    const float* __restrict__ iw0, const float* __restrict__ isig0, const float* __restrict__ imu0,
    const float* __restrict__ ierev0,
    const float* __restrict__ w0, const float* __restrict__ sig0, const float* __restrict__ mu0,
    const float* __restrict__ erev0, const float* __restrict__ gdiff0,
    const float* __restrict__ gleak1, const float* __restrict__ vleak1, const float* __restrict__ cm1,
    const float* __restrict__ iw1, const float* __restrict__ isig1, const float* __restrict__ imu1,
    const float* __restrict__ ierev1,
    const float* __restrict__ w1, const float* __restrict__ sig1, const float* __restrict__ mu1,
    const float* __restrict__ erev1, const float* __restrict__ gdiff1,
    float* __restrict__ d_out)
{
    int idx = blockIdx.x * blockDim.x + threadIdx.x;
    const float sdt = 0.40824829046386302f;  // sqrt(1/6)

    if (idx < NP0 * H0) {           // g_p0a
        int p = idx / H0, h = idx - p * H0;
        int i0 = (2 * p) * H0 + h, i1 = (2 * p + 1) * H0 + h;
        float s0 = 0.5f * sig0[i0], s1 = 0.5f * sig0[i1];
        float b0 = -s0 * 2.f * 0.5f * mu0[i0];   // = -0.5*sig*mu
        float b1 = -s1 * 2.f * 0.5f * mu0[i1];
        ulonglong2 o;
        o.x = packf2(s0, s1);
        o.y = packf2(b0, b1);
        g_p0a[idx] = o;
        return;
    }
    idx -= NP0 * H0;
    if (idx < NP0 * H0) {           // g_p0c
        int p = idx / H0, h = idx - p * H0;
        int i0 = (2 * p) * H0 + h, i1 = (2 * p + 1) * H0 + h;
        float wa = relu_(w0[i0]), wb = relu_(w0[i1]);
        ulonglong2 o;
        o.x = packf2(0.5f * wa * erev0[i0], 0.5f * wb * erev0[i1]);
        o.y = packf2(0.5f * wa, 0.5f * wb);
        g_p0c[idx] = o;
        return;
    }
    idx -= NP0 * H0;
    if (idx < H1 * H1) {            // g_d1 (fp32)
        float s = sig1[idx], m = mu1[idx], wv = relu_(w1[idx]);
        g_d1[idx] = make_float4(0.5f * s, -0.5f * s * m, 0.5f * wv * erev1[idx], 0.5f * wv);
        return;
    }
    idx -= H1 * H1;
    if (idx < H0 * H1) {            // g_din1 (fp32)
        float s = isig1[idx], m = imu1[idx], wv = relu_(iw1[idx]);
        g_din1[idx] = make_float4(0.5f * s, -0.5f * s * m, 0.5f * wv * ierev1[idx], 0.5f * wv);
        return;
    }
    idx -= H0 * H1;
    if (idx < H0) {
        float gl = relu_(gleak0[idx]);
        g_hc0[idx] = make_float4(gl * vleak0[idx], gl,
                                 1.0f / (relu_(cm0[idx]) + 1e-8f), gdiff0[idx] * sdt);
        return;
    }
    idx -= H0;
    if (idx < H1) {
        float gl = relu_(gleak1[idx]);
        g_hc1[idx] = make_float4(gl * vleak1[idx], gl,
                                 1.0f / (relu_(cm1[idx]) + 1e-8f), gdiff1[idx] * sdt);
        return;
    }
    idx -= H1;
    if (idx < H0) {   // g_sums0
        float sZ = 0.f, sW = 0.f;
        for (int i = 0; i < H0; ++i) {
            float wv = relu_(w0[i * H0 + idx]);
            sZ = fmaf(wv, erev0[i * H0 + idx], sZ);
            sW += wv;
        }
        g_sums0[idx] = make_float2(0.5f * sZ, 0.5f * sW);
        return;
    }
    idx -= H0;
    if (idx < H1) {   // g_sums1
        float sZ = 0.f, sW = 0.f;
        for (int i = 0; i < H1; ++i) {
            float wv = relu_(w1[i * H1 + idx]);
            sZ = fmaf(wv, erev1[i * H1 + idx], sZ);
            sW += wv;
        }
        g_sums1[idx] = make_float2(0.5f * sZ, 0.5f * sW);
        return;
    }
    idx -= H1;
    if (idx < H1) {   // g_sumsin1
        float sZ = 0.f, sW = 0.f;
        for (int i = 0; i < H0; ++i) {
            float wv = relu_(iw1[i * H1 + idx]);
            sZ = fmaf(wv, ierev1[i * H1 + idx], sZ);
            sW += wv;
        }
        g_sumsin1[idx] = make_float2(0.5f * sZ, 0.5f * sW);
        return;
    }
    idx -= H1;
    if (idx < B_ * H0) {   // exact layer0 input currents (fp32)
        int b = idx / H0, h = idx - b * H0;
        float an = 0.f, ad = 0.f;
        for (int i = 0; i < IN_; ++i) {
            int p = i * H0 + h;
            float y = -isig0[p] * (x[b * IN_ + i] - imu0[p]) * L2E;
            float sg = rcpf(1.f + ex2f(y));
            float a = relu_(iw0[p]) * sg;
            an = fmaf(a, ierev0[p], an);
            ad += a;
        }
        g_A0n[idx] = an;
        g_A0d[idx] = ad;
        return;
    }
    idx -= B_ * H0;
    if (idx < B_) {   // softmax weights
        float mx = -1e30f;
        for (int k = 0; k < K_; ++k) mx = fmaxf(mx, log_weights[idx * K_ + k]);
        float sum = 0.f;
        for (int k = 0; k < K_; ++k) sum += __expf(log_weights[idx * K_ + k] - mx);
        float inv = 1.0f / sum;
        for (int k = 0; k < K_; ++k)
            g_wts[idx * K_ + k] = __expf(log_weights[idx * K_ + k] - mx) * inv;
        return;
    }
    idx -= B_;
    if (idx < BK) {   // log_weights passthrough
        d_out[B_ * H1 + BK * HS + idx] = log_weights[idx];
        return;
    }
    idx -= BK;
    if (idx < B_) {
        g_cnt[idx] = 0;
        return;
    }
}

// ================= fused main kernel =================
// grid = 147 CTAs, block = 576 = 3 warpgroups x 192; group g handles i-pairs [32g, 32g+32)
__global__ void __launch_bounds__(NTHR, 1) main_kernel(
    const float* __restrict__ particles,
    const float* __restrict__ noise0,
    const float* __restrict__ noise1,
    float* __restrict__ out_particles,   // d_out + B_*H1
    float* __restrict__ out)             // d_out
{
    __shared__ u64   vsm0p[NP0][8];      // packed (v_2p, v_2p+1) per row r (padded to 8)
    __shared__ float vsm1[RMAX][H1];
    __shared__ float pN[3][RMAX][H0];
    __shared__ float pD[3][RMAX][H0];
    __shared__ int   sflag[2];

    const int c    = blockIdx.x;
    const int tid  = threadIdx.x;
    const int row0 = c * RMAX;
    const int R    = min(RMAX, BK - row0);

    // ---------- layer 0 ----------
    {
        const int g  = tid / H0;      // 0..2
        const int h  = tid - g * H0;  // 0..191
        const int p0 = g * 32;        // first i-pair of this group
        const float4 hc  = g_hc0[h];
        const float2 s0s = g_sums0[h];

        float vcur[RMAX], baseN[RMAX], baseD[RMAX];
        #pragma unroll
        for (int r = 0; r < RMAX; ++r) {
            int row = min(row0 + r, BK - 1);
            float v = particles[row * HS + h];
            vcur[r] = v;
            int b = row >> 6;
            baseN[r] = (g == 0) ? (g_A0n[b * H0 + h] + s0s.x) : 0.f;
            baseD[r] = (g == 0) ? (g_A0d[b * H0 + h] + s0s.y) : 0.f;
            if (g == 0) {
                float vo = __shfl_xor_sync(0xffffffffu, v, 1);
                if ((h & 1) == 0) vsm0p[h >> 1][r] = packf2(v, vo);
            }
        }
        __syncthreads();

        const ulonglong2* pa = &g_p0a[p0 * H0 + h];
        const ulonglong2* pcv = &g_p0c[p0 * H0 + h];

        for (int step = 0; step < UNF; ++step) {
            u64 aN2[RMAX], aD2[RMAX];
            #pragma unroll
            for (int r = 0; r < RMAX; ++r) { aN2[r] = 0ull; aD2[r] = 0ull; }

            #pragma unroll 1
            for (int pc = 0; pc < 32; pc += 4) {
                ulonglong2 A0 = ldcg2u64(pa + (pc + 0) * H0);
                ulonglong2 A1 = ldcg2u64(pa + (pc + 1) * H0);
                ulonglong2 A2 = ldcg2u64(pa + (pc + 2) * H0);
                ulonglong2 A3 = ldcg2u64(pa + (pc + 3) * H0);
                ulonglong2 C0 = ldcg2u64(pcv + (pc + 0) * H0);
                ulonglong2 C1 = ldcg2u64(pcv + (pc + 1) * H0);
                ulonglong2 C2 = ldcg2u64(pcv + (pc + 2) * H0);
                ulonglong2 C3 = ldcg2u64(pcv + (pc + 3) * H0);

                #pragma unroll
                for (int r = 0; r < RMAX; ++r) {
                    u64 v0 = vsm0p[p0 + pc + 0][r];
                    u64 v1 = vsm0p[p0 + pc + 1][r];
                    u64 v2 = vsm0p[p0 + pc + 2][r];
                    u64 v3 = vsm0p[p0 + pc + 3][r];
                    float f0, f1, f2, f3, f4, f5, f6, f7;
                    unpackf2(ffma2(A0.x, v0, A0.y), f0, f1);
                    unpackf2(ffma2(A1.x, v1, A1.y), f2, f3);
                    unpackf2(ffma2(A2.x, v2, A2.y), f4, f5);
                    unpackf2(ffma2(A3.x, v3, A3.y), f6, f7);
                    u64 t0 = packf2(tanhfast(f0), tanhfast(f1));
                    u64 t1 = packf2(tanhfast(f2), tanhfast(f3));
                    u64 t2 = packf2(tanhfast(f4), tanhfast(f5));
                    u64 t3 = packf2(tanhfast(f6), tanhfast(f7));
                    aN2[r] = ffma2(t0, C0.x, aN2[r]);  aD2[r] = ffma2(t0, C0.y, aD2[r]);
                    aN2[r] = ffma2(t1, C1.x, aN2[r]);  aD2[r] = ffma2(t1, C1.y, aD2[r]);
                    aN2[r] = ffma2(t2, C2.x, aN2[r]);  aD2[r] = ffma2(t2, C2.y, aD2[r]);
                    aN2[r] = ffma2(t3, C3.x, aN2[r]);  aD2[r] = ffma2(t3, C3.y, aD2[r]);
                }
            }
            #pragma unroll
            for (int r = 0; r < RMAX; ++r) {
                float nlo, nhi, dlo, dhi;
                unpackf2(aN2[r], nlo, nhi);
                unpackf2(aD2[r], dlo, dhi);
                pN[g][r][h] = baseN[r] + nlo + nhi;
                pD[g][r][h] = baseD[r] + dlo + dhi;
            }
            __syncthreads();

            #pragma unroll
            for (int r = 0; r < RMAX; ++r) {
                int row = min(row0 + r, BK - 1);
                float sumN = pN[0][r][h] + pN[1][r][h] + pN[2][r][h];
                float sumD = pD[0][r][h] + pD[1][r][h] + pD[2][r][h];
                float n = noise0[(step * BK + row) * H0 + h];
                float d = fmaf(-(hc.y + sumD), vcur[r], hc.x + sumN) * hc.z;
                vcur[r] = fmaf(d, (1.0f / 6.0f), fmaf(hc.w, n, vcur[r]));
                if (g == 0) {
                    float vo = __shfl_xor_sync(0xffffffffu, vcur[r], 1);
                    if ((h & 1) == 0) vsm0p[h >> 1][r] = packf2(vcur[r], vo);
                }
            }
            __syncthreads();
        }
        if (g == 0) {
            #pragma unroll
            for (int r = 0; r < RMAX; ++r)
                if (r < R) out_particles[(row0 + r) * HS + h] = vcur[r];
        }
    }

    // ---------- layer 1 ----------
    const int h1  = tid & 63;
    const int seg = tid >> 6;       // 0..8; seg < RMAX handles row (row0+seg)
    {
        const float4 hc  = g_hc1[h1];
        const float2 s1s = g_sums1[h1];
        const float2 sis = g_sumsin1[h1];

        for (int idx = tid; idx < RMAX * H1; idx += NTHR) {
            int r = idx >> 6, hh = idx & 63;
            int row = min(row0 + r, BK - 1);
            vsm1[r][hh] = particles[row * HS + H0 + hh];
        }
        __syncthreads();

        float ainN = 0.f, ainD = 0.f, vc = 0.f;
        if (seg < RMAX) {
            ainN = sis.x; ainD = sis.y;
            #pragma unroll 1
            for (int p = 0; p < NP0; p += 2) {
                float va, vb, vcc, vd;
                unpackf2(vsm0p[p][seg], va, vb);
                unpackf2(vsm0p[p + 1][seg], vcc, vd);
                float4 q0 = g_din1[(2 * p + 0) * H1 + h1];
                float4 q1 = g_din1[(2 * p + 1) * H1 + h1];
                float4 q2 = g_din1[(2 * p + 2) * H1 + h1];
                float4 q3 = g_din1[(2 * p + 3) * H1 + h1];
                float t0 = tanhfast(fmaf(q0.x, va, q0.y));
                float t1 = tanhfast(fmaf(q1.x, vb, q1.y));
                float t2 = tanhfast(fmaf(q2.x, vcc, q2.y));
                float t3 = tanhfast(fmaf(q3.x, vd, q3.y));
                ainN = fmaf(q0.z, t0, ainN); ainD = fmaf(q0.w, t0, ainD);
                ainN = fmaf(q1.z, t1, ainN); ainD = fmaf(q1.w, t1, ainD);
                ainN = fmaf(q2.z, t2, ainN); ainD = fmaf(q2.w, t2, ainD);
                ainN = fmaf(q3.z, t3, ainN); ainD = fmaf(q3.w, t3, ainD);
            }
            vc = vsm1[seg][h1];
        }

        for (int step = 0; step < UNF; ++step) {
            float nv = 0.f;
            if (seg < RMAX) {
                float accN = ainN + s1s.x;
                float accD = ainD + s1s.y;
                #pragma unroll 4
                for (int i = 0; i < H1; ++i) {
                    float4 p = g_d1[i * H1 + h1];   // 64KB, L1-resident
                    float t = tanhfast(fmaf(p.x, vsm1[seg][i], p.y));
                    accN = fmaf(p.z, t, accN);
                    accD = fmaf(p.w, t, accD);
                }
                int row = min(row0 + seg, BK - 1);
                float n = noise1[(step * BK + row) * H1 + h1];
                float d = fmaf(-(hc.y + accD), vc, hc.x + accN) * hc.z;
                nv = fmaf(d, (1.0f / 6.0f), fmaf(hc.w, n, vc));
            }
            __syncthreads();
            if (seg < RMAX) { vsm1[seg][h1] = nv; vc = nv; }
            __syncthreads();
        }

        if (seg < RMAX) {
            int row = row0 + seg;
            if (row < BK) {
                out_particles[row * HS + H0 + h1] = vc;
                g_s1[row * H1 + h1] = vc;
            }
        }
    }

    // ---------- output (last CTA per b reduces) ----------
    __threadfence();
    __syncthreads();
    if (tid == 0) {
        sflag[0] = -1; sflag[1] = -1;
        int b0 = row0 >> 6, b1 = (row0 + R - 1) >> 6;
        int k = 0;
        for (int b = b0; b <= b1; ++b) {
            int cf = (b * K_) / RMAX;
            int cl = min(NCTA - 1, (b * K_ + 63) / RMAX);
            int tgt = cl - cf + 1;
            int old = atomicAdd(&g_cnt[b], 1);
            sflag[k++] = (old == tgt - 1) ? b : -1;
        }
    }
    __syncthreads();
    __threadfence();
    #pragma unroll
    for (int k = 0; k < 2; ++k) {
        int b = sflag[k];
        if (b >= 0 && tid < K_) {
            float acc = 0.f;
            #pragma unroll 8
            for (int kk = 0; kk < K_; ++kk)
                acc = fmaf(g_wts[b * K_ + kk], __ldcg(&g_s1[(b * K_ + kk) * H1 + tid]), acc);
            out[b * H1 + tid] = acc;
        }
    }
}

// ================= launch =================
extern "C" void kernel_launch(void* const* d_in, const int* in_sizes, int n_in,
                              void* d_out, int out_size)
{
    const float* x           = (const float*)d_in[0];
    const float* particles   = (const float*)d_in[1];
    const float* log_weights = (const float*)d_in[2];
    const float* noise0      = (const float*)d_in[3];
    const float* noise1      = (const float*)d_in[4];

    const int total = 2 * NP0 * H0 + H1 * H1 + H0 * H1 + H0 + H1 + H0 + H1 + H1
                    + B_ * H0 + B_ + BK + B_;
    precompute_kernel<<<(total + 255) / 256, 256>>>(
        x, log_weights,
        (const float*)d_in[5],  (const float*)d_in[6],  (const float*)d_in[7],
        (const float*)d_in[8],  (const float*)d_in[9],  (const float*)d_in[10],
        (const float*)d_in[11],
        (const float*)d_in[12], (const float*)d_in[13], (const float*)d_in[14],
        (const float*)d_in[15], (const float*)d_in[16],
        (const float*)d_in[17], (const float*)d_in[18], (const float*)d_in[19],
        (const float*)d_in[20], (const float*)d_in[21], (const float*)d_in[22],
        (const float*)d_in[23],
        (const float*)d_in[24], (const float*)d_in[25], (const float*)d_in[26],
        (const float*)d_in[27], (const float*)d_in[28],
        (float*)d_out);

    float* out = (float*)d_out;
    main_kernel<<<NCTA, NTHR>>>(particles, noise0, noise1, out + B_ * H1, out);
}